// round 4
// baseline (speedup 1.0000x reference)
#include <cuda_runtime.h>
#include <cuda_bf16.h>
#include <cstdint>

// Greedy CTC decode, fused:
//   emission: [T, V=128] fp32
//   out (fp32, 3*T): [ idx(0:T) | keep(T:2T) | path_score(2T:3T) ]
//
// Kernel 1 (fused): warp handles 8 consecutive rows (R2 structure: 8
//   front-batched LDG.128 = MLP 8, REDUX+ballot warp argmax). Dedup is done
//   in-register for rows 1..7; warp row 0 gets prev from the preceding warp
//   via smem. Block's first row is written tentatively with prev=-1.
// Kernel 2 (fixup): for the 1-per-64 block-boundary rows, clear keep/score
//   where idx[t]==idx[t-1] (clear-only; kept rows already hold max).

#define V 128
#define BLANK 0
#define WARPS_PER_BLOCK 8
#define ROWS_PER_WARP 8
#define ROWS_PER_BLOCK (WARPS_PER_BLOCK * ROWS_PER_WARP)   // 64
#define FULL_MASK 0xFFFFFFFFu

// Order-preserving fp32 bits -> u32 map and inverse.
__device__ __forceinline__ unsigned fmono(float f) {
    unsigned b = __float_as_uint(f);
    return b ^ ((unsigned)((int)b >> 31) | 0x80000000u);
}
__device__ __forceinline__ float funmono(unsigned u) {
    unsigned b = u ^ ((unsigned)((int)(~u) >> 31) | 0x80000000u);
    return __uint_as_float(b);
}

__global__ void __launch_bounds__(WARPS_PER_BLOCK * 32)
ctc_fused_kernel(const float* __restrict__ em,
                 float* __restrict__ out_idx,
                 float* __restrict__ out_keep,
                 float* __restrict__ out_score,
                 int rows)
{
    __shared__ float s_last[WARPS_PER_BLOCK];   // last idx of each warp's tile

    const int lane = threadIdx.x & 31;
    const int warp = threadIdx.x >> 5;
    const int base = blockIdx.x * ROWS_PER_BLOCK + warp * ROWS_PER_WARP;
    if (base >= rows) return;

    // Front-batched loads: 8 independent LDG.128, 4KB contiguous per warp.
    float4 v[ROWS_PER_WARP];
    #pragma unroll
    for (int k = 0; k < ROWS_PER_WARP; k++) {
        v[k] = reinterpret_cast<const float4*>(em + (size_t)(base + k) * V)[lane];
    }

    float res_idx[ROWS_PER_WARP];
    float res_max[ROWS_PER_WARP];

    #pragma unroll
    for (int k = 0; k < ROWS_PER_WARP; k++) {
        float best = v[k].x; int bi = lane * 4;
        if (v[k].y > best) { best = v[k].y; bi = lane * 4 + 1; }
        if (v[k].z > best) { best = v[k].z; bi = lane * 4 + 2; }
        if (v[k].w > best) { best = v[k].w; bi = lane * 4 + 3; }

        unsigned key  = fmono(best);
        unsigned wmax = __reduce_max_sync(FULL_MASK, key);
        unsigned ball = __ballot_sync(FULL_MASK, key == wmax);
        int src  = __ffs(ball) - 1;              // lowest lane = lowest column
        int widx = __shfl_sync(FULL_MASK, bi, src);

        res_idx[k] = (float)widx;
        res_max[k] = funmono(wmax);
    }

    // Exchange warp-tile last idx for cross-warp prev.
    if (lane == 0) s_last[warp] = res_idx[ROWS_PER_WARP - 1];
    __syncthreads();

    if (lane == 0) {
        // prev for this warp's row 0. Warp 0: tentative -1 (block's first row
        // fixed by fixup kernel for blockIdx.x > 0; exact for block 0 / t=0).
        float prev = (warp > 0) ? s_last[warp - 1] : -1.0f;

        float kp[ROWS_PER_WARP], sc[ROWS_PER_WARP];
        #pragma unroll
        for (int k = 0; k < ROWS_PER_WARP; k++) {
            float cur = res_idx[k];
            bool keep = (cur != prev) && (cur != (float)BLANK);
            kp[k] = keep ? 1.0f : 0.0f;
            sc[k] = keep ? res_max[k] : 0.0f;
            prev = cur;
        }

        // base is a multiple of 8 -> 16B-aligned float4 stores
        reinterpret_cast<float4*>(out_idx + base)[0] =
            make_float4(res_idx[0], res_idx[1], res_idx[2], res_idx[3]);
        reinterpret_cast<float4*>(out_idx + base)[1] =
            make_float4(res_idx[4], res_idx[5], res_idx[6], res_idx[7]);
        reinterpret_cast<float4*>(out_keep + base)[0] =
            make_float4(kp[0], kp[1], kp[2], kp[3]);
        reinterpret_cast<float4*>(out_keep + base)[1] =
            make_float4(kp[4], kp[5], kp[6], kp[7]);
        reinterpret_cast<float4*>(out_score + base)[0] =
            make_float4(sc[0], sc[1], sc[2], sc[3]);
        reinterpret_cast<float4*>(out_score + base)[1] =
            make_float4(sc[4], sc[5], sc[6], sc[7]);
    }
}

// Clear-only fixup for block-boundary rows t = 64, 128, ...:
// if idx[t] == idx[t-1], the tentative keep=1/score=max must become 0.
__global__ void __launch_bounds__(256)
ctc_fixup_kernel(const float* __restrict__ idx_f,
                 float* __restrict__ keep_f,
                 float* __restrict__ score_f,
                 int nboundary)
{
    int i = blockIdx.x * blockDim.x + threadIdx.x;
    if (i >= nboundary) return;
    int t = (i + 1) * ROWS_PER_BLOCK;
    float cur = idx_f[t];
    if (cur == idx_f[t - 1] && cur != (float)BLANK) {
        keep_f[t]  = 0.0f;
        score_f[t] = 0.0f;
    }
}

extern "C" void kernel_launch(void* const* d_in, const int* in_sizes, int n_in,
                              void* d_out, int out_size)
{
    const float* em = (const float*)d_in[0];
    float* out = (float*)d_out;

    const int rows = in_sizes[0] / V;            // T = 1048576
    float* out_idx   = out;                      // [0:T)
    float* out_keep  = out + rows;               // [T:2T)
    float* out_score = out + 2 * (size_t)rows;   // [2T:3T)

    {
        dim3 block(WARPS_PER_BLOCK * 32);
        dim3 grid((rows + ROWS_PER_BLOCK - 1) / ROWS_PER_BLOCK);
        ctc_fused_kernel<<<grid, block>>>(em, out_idx, out_keep, out_score, rows);
    }
    {
        int nboundary = rows / ROWS_PER_BLOCK - 1;   // 16383
        dim3 block(256);
        dim3 grid((nboundary + 255) / 256);
        ctc_fixup_kernel<<<grid, block>>>(out_idx, out_keep, out_score, nboundary);
    }
}